// round 15
// baseline (speedup 1.0000x reference)
#include <cuda_runtime.h>
#include <cuda_fp16.h>
#include <cstdint>

// ---------------- problem constants ----------------
#define BATCH 8192
#define INSZ  1024
#define HID   2048
#define NG    6144            // 3*HID
#define KTOT  3072            // INSZ + HID
#define KITERS 48             // K-chunks of 64 halfs
#define STAGES 3

// Fused CTA tile: 64(M) x 64(N_hid) x 3 gates, 4 warps (2x2), warp tile 32x32/gate
// stage: A 64x64h (8KB) + B 3x64x64h (24KB) = 32KB; 2 CTAs/SM
#define STAGE_BYTES  32768
#define SMEM_TOTAL (STAGES * STAGE_BYTES)   // 98304 per CTA

// scratch (static device arrays are allowed)
__device__ __half g_BT[(size_t)NG * KTOT];       // [W;Wh]^T K-major, half
__device__ __half g_AH[(size_t)BATCH * KTOT];    // [X|H] merged, half

// ---------------- ptx helpers ----------------
#define CP_ASYNC16(dst, src) \
    asm volatile("cp.async.cg.shared.global [%0], [%1], 16;" :: "r"(dst), "l"(src))
#define CP_COMMIT() asm volatile("cp.async.commit_group;" ::: "memory")
#define CP_WAIT1()  asm volatile("cp.async.wait_group 1;" ::: "memory")

#define LDSM4(r0, r1, r2, r3, addr) \
    asm volatile("ldmatrix.sync.aligned.m8n8.x4.shared.b16 {%0,%1,%2,%3}, [%4];" \
        : "=r"(r0), "=r"(r1), "=r"(r2), "=r"(r3) : "r"(addr))

#define MMA_F16(d, a, b) \
    asm volatile("mma.sync.aligned.m16n8k16.row.col.f32.f16.f16.f32 " \
        "{%0,%1,%2,%3}, {%4,%5,%6,%7}, {%8,%9}, {%0,%1,%2,%3};" \
        : "+f"((d)[0]), "+f"((d)[1]), "+f"((d)[2]), "+f"((d)[3]) \
        : "r"((a)[0]), "r"((a)[1]), "r"((a)[2]), "r"((a)[3]), \
          "r"((b)[0]), "r"((b)[1]))

__device__ __forceinline__ float fast_sigmoid(float x) {
    return __fdividef(1.f, 1.f + __expf(-x));
}
__device__ __forceinline__ float fast_tanh(float x) {
    return __fdividef(2.f, 1.f + __expf(-2.f * x)) - 1.f;
}

// ---------------- kernel 1: merged prep ----------------
#define CVT_BLOCKS  (BATCH * (KTOT / 8) / 256)   // 12288
#define PACK_BLOCKS ((KTOT / 32) * (NG / 128))   // 4608

__global__ void __launch_bounds__(256) lstm_prep(
    const float* __restrict__ X, const float* __restrict__ H,
    const float* __restrict__ W, const float* __restrict__ Wh,
    __half* __restrict__ AH, __half* __restrict__ BT) {
    __shared__ float s[32 * 129];
    const int tid = threadIdx.x;

    if (blockIdx.x < CVT_BLOCKS) {
        int t = blockIdx.x * 256 + tid;
        int m = t / (KTOT / 8);
        int col = (t % (KTOT / 8)) * 8;
        const float* src = (col < INSZ) ? (X + (size_t)m * INSZ + col)
                                        : (H + (size_t)m * HID + (col - INSZ));
        float4 v0 = ((const float4*)src)[0];
        float4 v1 = ((const float4*)src)[1];
        __half2 h0 = __floats2half2_rn(v0.x, v0.y);
        __half2 h1 = __floats2half2_rn(v0.z, v0.w);
        __half2 h2 = __floats2half2_rn(v1.x, v1.y);
        __half2 h3 = __floats2half2_rn(v1.z, v1.w);
        uint4 u;
        u.x = *reinterpret_cast<uint32_t*>(&h0);
        u.y = *reinterpret_cast<uint32_t*>(&h1);
        u.z = *reinterpret_cast<uint32_t*>(&h2);
        u.w = *reinterpret_cast<uint32_t*>(&h3);
        *(uint4*)(AH + (size_t)m * KTOT + col) = u;
        return;
    }

    const int pb = blockIdx.x - CVT_BLOCKS;
    const int k0 = (pb % (KTOT / 32)) * 32;
    const int n0 = (pb / (KTOT / 32)) * 128;

    #pragma unroll
    for (int i = 0; i < 4; i++) {
        int idx = tid + i * 256;
        int r = idx >> 5;
        int c4 = idx & 31;
        int k = k0 + r;
        const float* src = (k < INSZ) ? (W + (size_t)k * NG + n0 + c4 * 4)
                                      : (Wh + (size_t)(k - INSZ) * NG + n0 + c4 * 4);
        float4 v = *(const float4*)src;
        s[r * 129 + c4 * 4 + 0] = v.x;
        s[r * 129 + c4 * 4 + 1] = v.y;
        s[r * 129 + c4 * 4 + 2] = v.z;
        s[r * 129 + c4 * 4 + 3] = v.w;
    }
    __syncthreads();
    #pragma unroll
    for (int i = 0; i < 4; i++) {
        int idx = tid + i * 256;
        int n = idx >> 3;
        int kg = idx & 7;
        __half2 p0 = __floats2half2_rn(s[(kg * 4 + 0) * 129 + n], s[(kg * 4 + 1) * 129 + n]);
        __half2 p1 = __floats2half2_rn(s[(kg * 4 + 2) * 129 + n], s[(kg * 4 + 3) * 129 + n]);
        uint2 u;
        u.x = *reinterpret_cast<uint32_t*>(&p0);
        u.y = *reinterpret_cast<uint32_t*>(&p1);
        *(uint2*)(BT + (size_t)(n0 + n) * KTOT + k0 + kg * 4) = u;
    }
}

// ---------------- kernel 2: fused fp16 GEMM (3 gates) + LSTM epilogue ----------------
__global__ void __launch_bounds__(128, 2) lstm_gemm_fused(
    const __half* __restrict__ AH, const __half* __restrict__ BT,
    const float* __restrict__ c0, const float* __restrict__ bias,
    float* __restrict__ out) {
    extern __shared__ char smem[];
    const int tid = threadIdx.x;
    const int lane = tid & 31, wid = tid >> 5;
    const int wm = wid & 1, wn = wid >> 1;            // 2x2 warp grid, 32x32 warp tile/gate
    const int m0 = blockIdx.y * 64, n0 = blockIdx.x * 64;

    const uint32_t sbase = (uint32_t)__cvta_generic_to_shared(smem);

    float acc[3][2][4][4];                            // [gate][mb][nb][4]
    #pragma unroll
    for (int g = 0; g < 3; g++)
        #pragma unroll
        for (int i = 0; i < 2; i++)
            #pragma unroll
            for (int j = 0; j < 4; j++)
                #pragma unroll
                for (int k = 0; k < 4; k++) acc[g][i][j][k] = 0.f;

    const int a_moff = ((lane >> 3) & 1) * 8 + (lane & 7);
    const int a_csel = lane >> 4;
    const int b_noff = ((lane >> 4) & 1) * 8 + (lane & 7);
    const int b_csel = (lane >> 3) & 1;

    // stage: A rows 0..63 (128B each), then B rows 0..191 (gate g at rows g*64..)
    auto load_stage = [&](int kc, int s) {
        const uint32_t As = sbase + s * STAGE_BYTES;
        const uint32_t Bs = As + 8192;
        #pragma unroll
        for (int i = 0; i < 4; i++) {
            int ch = tid + i * 128;                    // 0..511
            int m = ch >> 3, c = ch & 7;
            const __half* src = AH + (size_t)(m0 + m) * KTOT + kc * 64 + c * 8;
            uint32_t dst = As + m * 128 + ((c ^ (m & 7)) << 4);
            CP_ASYNC16(dst, src);
        }
        #pragma unroll
        for (int i = 0; i < 12; i++) {
            int ch = tid + i * 128;                    // 0..1535
            int r = ch >> 3, c = ch & 7;               // r: 0..191
            int g = r >> 6, n = r & 63;
            const __half* src = BT + (size_t)(g * HID + n0 + n) * KTOT + kc * 64 + c * 8;
            uint32_t dst = Bs + r * 128 + ((c ^ (r & 7)) << 4);
            CP_ASYNC16(dst, src);
        }
    };

    auto load_afrag = [&](uint32_t As, int kk, uint32_t a[2][4]) {
        #pragma unroll
        for (int mb = 0; mb < 2; mb++) {
            int m = wm * 32 + mb * 16 + a_moff;
            int c = kk * 2 + a_csel;
            uint32_t addr = As + m * 128 + ((c ^ (m & 7)) << 4);
            LDSM4(a[mb][0], a[mb][1], a[mb][2], a[mb][3], addr);
        }
    };
    auto load_bfrag = [&](uint32_t Bs, int kk, uint32_t b[3][4][2]) {
        #pragma unroll
        for (int g = 0; g < 3; g++) {
            #pragma unroll
            for (int p = 0; p < 2; p++) {
                int r = g * 64 + wn * 32 + p * 16 + b_noff;
                int c = kk * 2 + b_csel;
                uint32_t addr = Bs + r * 128 + ((c ^ (r & 7)) << 4);
                LDSM4(b[g][2 * p][0], b[g][2 * p][1], b[g][2 * p + 1][0], b[g][2 * p + 1][1], addr);
            }
        }
    };

    // prologue: fill 2 of 3 stages
    #pragma unroll
    for (int s = 0; s < STAGES - 1; s++) { load_stage(s, s); CP_COMMIT(); }

    uint32_t afr[2][2][4], bfr[2][3][4][2];

    // epilogue operand prefetch registers (c0 tile), filled before the last chunk
    const int gr = lane >> 2, tig = lane & 3;
    float2 c0pre[2][4][2];                             // [mb][nb][row-half]

    for (int kc = 0; kc < KITERS; kc++) {
        CP_WAIT1();
        __syncthreads();

        const uint32_t As = sbase + (kc % STAGES) * STAGE_BYTES;
        const uint32_t Bs = As + 8192;

        // MMA-feeding LDSMs first; cp.async burst for kc+2 hides under MMAs.
        load_afrag(As, 0, afr[0]);
        load_bfrag(Bs, 0, bfr[0]);

        int ls = kc + STAGES - 1;
        if (ls < KITERS) load_stage(ls, ls % STAGES);   // writes slot (kc+2)%3 != (kc)%3
        CP_COMMIT();

        // before the final chunk's MMA burst, issue the epilogue c0 loads so
        // their gmem latency hides under ~1500 cyc of MMA work.
        if (kc == KITERS - 1) {
            #pragma unroll
            for (int mb = 0; mb < 2; mb++) {
                int row0 = m0 + wm * 32 + mb * 16 + gr;
                #pragma unroll
                for (int nb = 0; nb < 4; nb++) {
                    int col = n0 + wn * 32 + nb * 8 + tig * 2;
                    c0pre[mb][nb][0] = __ldg((const float2*)(c0 + (size_t)row0 * HID + col));
                    c0pre[mb][nb][1] = __ldg((const float2*)(c0 + (size_t)(row0 + 8) * HID + col));
                }
            }
        }

        #pragma unroll
        for (int kk = 0; kk < 4; kk++) {
            int cur = kk & 1, nxt = cur ^ 1;
            if (kk < 3) {
                load_afrag(As, kk + 1, afr[nxt]);
                load_bfrag(Bs, kk + 1, bfr[nxt]);
            }
            #pragma unroll
            for (int g = 0; g < 3; g++)
                #pragma unroll
                for (int mb = 0; mb < 2; mb++)
                    #pragma unroll
                    for (int nb = 0; nb < 4; nb++)
                        MMA_F16(acc[g][mb][nb], afr[cur][mb], bfr[cur][g][nb]);
        }
    }

    // ---- fused LSTM epilogue: c1 = sig(f+bf)*c0 + sig(i+bi)*tanh(c+bc) ----
    #pragma unroll
    for (int mb = 0; mb < 2; mb++) {
        int row0 = m0 + wm * 32 + mb * 16 + gr;       // rows row0 and row0+8
        #pragma unroll
        for (int nb = 0; nb < 4; nb++) {
            int col = n0 + wn * 32 + nb * 8 + tig * 2;
            float2 bf = *(const float2*)(bias + col);
            float2 bi = *(const float2*)(bias + HID + col);
            float2 bc = *(const float2*)(bias + 2 * HID + col);
            float2 c0a = c0pre[mb][nb][0];
            float2 c0b = c0pre[mb][nb][1];

            const float* F = acc[0][mb][nb];
            const float* I = acc[1][mb][nb];
            const float* C = acc[2][mb][nb];

            float2 o0, o1;
            o0.x = fast_sigmoid(F[0] + bf.x) * c0a.x +
                   fast_sigmoid(I[0] + bi.x) * fast_tanh(C[0] + bc.x);
            o0.y = fast_sigmoid(F[1] + bf.y) * c0a.y +
                   fast_sigmoid(I[1] + bi.y) * fast_tanh(C[1] + bc.y);
            o1.x = fast_sigmoid(F[2] + bf.x) * c0b.x +
                   fast_sigmoid(I[2] + bi.x) * fast_tanh(C[2] + bc.x);
            o1.y = fast_sigmoid(F[3] + bf.y) * c0b.y +
                   fast_sigmoid(I[3] + bi.y) * fast_tanh(C[3] + bc.y);

            *(float2*)(out + (size_t)row0 * HID + col) = o0;
            *(float2*)(out + (size_t)(row0 + 8) * HID + col) = o1;
        }
    }
}

// ---------------- host launch ----------------
extern "C" void kernel_launch(void* const* d_in, const int* in_sizes, int n_in,
                              void* d_out, int out_size) {
    const float* X    = (const float*)d_in[0];
    const float* H0   = (const float*)d_in[1];
    const float* C0   = (const float*)d_in[2];
    const float* W    = (const float*)d_in[3];
    const float* Wh   = (const float*)d_in[4];
    const float* Bias = (const float*)d_in[5];
    float* out = (float*)d_out;

    __half* bt = nullptr;
    __half* ah = nullptr;
    cudaGetSymbolAddress((void**)&bt, g_BT);
    cudaGetSymbolAddress((void**)&ah, g_AH);

    cudaFuncSetAttribute(lstm_gemm_fused, cudaFuncAttributeMaxDynamicSharedMemorySize,
                         SMEM_TOTAL);

    lstm_prep<<<CVT_BLOCKS + PACK_BLOCKS, 256>>>(X, H0, W, Wh, ah, bt);
    lstm_gemm_fused<<<dim3(HID / 64, BATCH / 64), 128, SMEM_TOTAL>>>(ah, bt, C0, Bias, out);
}

// round 16
// speedup vs baseline: 1.0465x; 1.0465x over previous
#include <cuda_runtime.h>
#include <cuda_fp16.h>
#include <cstdint>

// ---------------- problem constants ----------------
#define BATCH 8192
#define INSZ  1024
#define HID   2048
#define NG    6144            // 3*HID
#define KTOT  3072            // INSZ + HID
#define KITERS 48             // K-chunks of 64 halfs
#define STAGES 3

// Fused CTA tile: 64(M) x 64(N_hid) x 3 gates, 4 warps (2x2), warp tile 32x32/gate
// stage: A 64x64h (8KB) + B 3x64x64h (24KB) = 32KB; 2 CTAs/SM (verified occ=12.3% = 8 warps/SM)
#define STAGE_BYTES  32768
#define SMEM_TOTAL (STAGES * STAGE_BYTES)   // 98304 per CTA

// scratch (static device arrays are allowed)
__device__ __half g_BT[(size_t)NG * KTOT];       // [W;Wh]^T K-major, half
__device__ __half g_AH[(size_t)BATCH * KTOT];    // [X|H] merged, half

// ---------------- ptx helpers ----------------
#define CP_ASYNC16(dst, src) \
    asm volatile("cp.async.cg.shared.global [%0], [%1], 16;" :: "r"(dst), "l"(src))
#define CP_COMMIT() asm volatile("cp.async.commit_group;" ::: "memory")
#define CP_WAIT1()  asm volatile("cp.async.wait_group 1;" ::: "memory")

#define LDSM4(r0, r1, r2, r3, addr) \
    asm volatile("ldmatrix.sync.aligned.m8n8.x4.shared.b16 {%0,%1,%2,%3}, [%4];" \
        : "=r"(r0), "=r"(r1), "=r"(r2), "=r"(r3) : "r"(addr))

#define MMA_F16(d, a, b) \
    asm volatile("mma.sync.aligned.m16n8k16.row.col.f32.f16.f16.f32 " \
        "{%0,%1,%2,%3}, {%4,%5,%6,%7}, {%8,%9}, {%0,%1,%2,%3};" \
        : "+f"((d)[0]), "+f"((d)[1]), "+f"((d)[2]), "+f"((d)[3]) \
        : "r"((a)[0]), "r"((a)[1]), "r"((a)[2]), "r"((a)[3]), \
          "r"((b)[0]), "r"((b)[1]))

__device__ __forceinline__ float fast_sigmoid(float x) {
    return __fdividef(1.f, 1.f + __expf(-x));
}
__device__ __forceinline__ float fast_tanh(float x) {
    return __fdividef(2.f, 1.f + __expf(-2.f * x)) - 1.f;
}

// ---------------- kernel 1: merged prep ----------------
// blocks [0, CVT_BLOCKS):            convert [X|H] -> AH (half)
// blocks [CVT_BLOCKS, +PACK_BLOCKS): pack [W;Wh] -> BT[n][k] (K-major half)
#define CVT_BLOCKS  (BATCH * (KTOT / 8) / 256)   // 12288
#define PACK_BLOCKS ((KTOT / 32) * (NG / 128))   // 4608

__global__ void __launch_bounds__(256) lstm_prep(
    const float* __restrict__ X, const float* __restrict__ H,
    const float* __restrict__ W, const float* __restrict__ Wh,
    __half* __restrict__ AH, __half* __restrict__ BT) {
    __shared__ float s[32 * 129];
    const int tid = threadIdx.x;

    if (blockIdx.x < CVT_BLOCKS) {
        int t = blockIdx.x * 256 + tid;
        int m = t / (KTOT / 8);
        int col = (t % (KTOT / 8)) * 8;
        const float* src = (col < INSZ) ? (X + (size_t)m * INSZ + col)
                                        : (H + (size_t)m * HID + (col - INSZ));
        float4 v0 = ((const float4*)src)[0];
        float4 v1 = ((const float4*)src)[1];
        __half2 h0 = __floats2half2_rn(v0.x, v0.y);
        __half2 h1 = __floats2half2_rn(v0.z, v0.w);
        __half2 h2 = __floats2half2_rn(v1.x, v1.y);
        __half2 h3 = __floats2half2_rn(v1.z, v1.w);
        uint4 u;
        u.x = *reinterpret_cast<uint32_t*>(&h0);
        u.y = *reinterpret_cast<uint32_t*>(&h1);
        u.z = *reinterpret_cast<uint32_t*>(&h2);
        u.w = *reinterpret_cast<uint32_t*>(&h3);
        *(uint4*)(AH + (size_t)m * KTOT + col) = u;
        return;
    }

    const int pb = blockIdx.x - CVT_BLOCKS;
    const int k0 = (pb % (KTOT / 32)) * 32;
    const int n0 = (pb / (KTOT / 32)) * 128;

    #pragma unroll
    for (int i = 0; i < 4; i++) {
        int idx = tid + i * 256;
        int r = idx >> 5;
        int c4 = idx & 31;
        int k = k0 + r;
        const float* src = (k < INSZ) ? (W + (size_t)k * NG + n0 + c4 * 4)
                                      : (Wh + (size_t)(k - INSZ) * NG + n0 + c4 * 4);
        float4 v = *(const float4*)src;
        s[r * 129 + c4 * 4 + 0] = v.x;
        s[r * 129 + c4 * 4 + 1] = v.y;
        s[r * 129 + c4 * 4 + 2] = v.z;
        s[r * 129 + c4 * 4 + 3] = v.w;
    }
    __syncthreads();
    #pragma unroll
    for (int i = 0; i < 4; i++) {
        int idx = tid + i * 256;
        int n = idx >> 3;
        int kg = idx & 7;
        __half2 p0 = __floats2half2_rn(s[(kg * 4 + 0) * 129 + n], s[(kg * 4 + 1) * 129 + n]);
        __half2 p1 = __floats2half2_rn(s[(kg * 4 + 2) * 129 + n], s[(kg * 4 + 3) * 129 + n]);
        uint2 u;
        u.x = *reinterpret_cast<uint32_t*>(&p0);
        u.y = *reinterpret_cast<uint32_t*>(&p1);
        *(uint2*)(BT + (size_t)(n0 + n) * KTOT + k0 + kg * 4) = u;
    }
}

// ---------------- kernel 2: fused fp16 GEMM (3 gates) + LSTM epilogue ----------------
// Best measured configuration (R13): 128 threads, 2 CTAs/SM, LDSM-before-cp.async chunk head.
__global__ void __launch_bounds__(128, 2) lstm_gemm_fused(
    const __half* __restrict__ AH, const __half* __restrict__ BT,
    const float* __restrict__ c0, const float* __restrict__ bias,
    float* __restrict__ out) {
    extern __shared__ char smem[];
    const int tid = threadIdx.x;
    const int lane = tid & 31, wid = tid >> 5;
    const int wm = wid & 1, wn = wid >> 1;            // 2x2 warp grid, 32x32 warp tile/gate
    const int m0 = blockIdx.y * 64, n0 = blockIdx.x * 64;

    const uint32_t sbase = (uint32_t)__cvta_generic_to_shared(smem);

    float acc[3][2][4][4];                            // [gate][mb][nb][4]
    #pragma unroll
    for (int g = 0; g < 3; g++)
        #pragma unroll
        for (int i = 0; i < 2; i++)
            #pragma unroll
            for (int j = 0; j < 4; j++)
                #pragma unroll
                for (int k = 0; k < 4; k++) acc[g][i][j][k] = 0.f;

    const int a_moff = ((lane >> 3) & 1) * 8 + (lane & 7);
    const int a_csel = lane >> 4;
    const int b_noff = ((lane >> 4) & 1) * 8 + (lane & 7);
    const int b_csel = (lane >> 3) & 1;

    // stage: A rows 0..63 (128B each), then B rows 0..191 (gate g at rows g*64..)
    auto load_stage = [&](int kc, int s) {
        const uint32_t As = sbase + s * STAGE_BYTES;
        const uint32_t Bs = As + 8192;
        #pragma unroll
        for (int i = 0; i < 4; i++) {
            int ch = tid + i * 128;                    // 0..511
            int m = ch >> 3, c = ch & 7;
            const __half* src = AH + (size_t)(m0 + m) * KTOT + kc * 64 + c * 8;
            uint32_t dst = As + m * 128 + ((c ^ (m & 7)) << 4);
            CP_ASYNC16(dst, src);
        }
        #pragma unroll
        for (int i = 0; i < 12; i++) {
            int ch = tid + i * 128;                    // 0..1535
            int r = ch >> 3, c = ch & 7;               // r: 0..191
            int g = r >> 6, n = r & 63;
            const __half* src = BT + (size_t)(g * HID + n0 + n) * KTOT + kc * 64 + c * 8;
            uint32_t dst = Bs + r * 128 + ((c ^ (r & 7)) << 4);
            CP_ASYNC16(dst, src);
        }
    };

    auto load_afrag = [&](uint32_t As, int kk, uint32_t a[2][4]) {
        #pragma unroll
        for (int mb = 0; mb < 2; mb++) {
            int m = wm * 32 + mb * 16 + a_moff;
            int c = kk * 2 + a_csel;
            uint32_t addr = As + m * 128 + ((c ^ (m & 7)) << 4);
            LDSM4(a[mb][0], a[mb][1], a[mb][2], a[mb][3], addr);
        }
    };
    auto load_bfrag = [&](uint32_t Bs, int kk, uint32_t b[3][4][2]) {
        #pragma unroll
        for (int g = 0; g < 3; g++) {
            #pragma unroll
            for (int p = 0; p < 2; p++) {
                int r = g * 64 + wn * 32 + p * 16 + b_noff;
                int c = kk * 2 + b_csel;
                uint32_t addr = Bs + r * 128 + ((c ^ (r & 7)) << 4);
                LDSM4(b[g][2 * p][0], b[g][2 * p][1], b[g][2 * p + 1][0], b[g][2 * p + 1][1], addr);
            }
        }
    };

    // prologue: fill 2 of 3 stages
    #pragma unroll
    for (int s = 0; s < STAGES - 1; s++) { load_stage(s, s); CP_COMMIT(); }

    uint32_t afr[2][2][4], bfr[2][3][4][2];

    for (int kc = 0; kc < KITERS; kc++) {
        CP_WAIT1();
        __syncthreads();

        const uint32_t As = sbase + (kc % STAGES) * STAGE_BYTES;
        const uint32_t Bs = As + 8192;

        // MMA-feeding LDSMs first, so the first MMA issues ~130cyc earlier;
        // the cp.async burst for chunk kc+2 then hides under MMA execution.
        load_afrag(As, 0, afr[0]);
        load_bfrag(Bs, 0, bfr[0]);

        int ls = kc + STAGES - 1;
        if (ls < KITERS) load_stage(ls, ls % STAGES);   // writes slot (kc+2)%3 != (kc)%3
        CP_COMMIT();

        #pragma unroll
        for (int kk = 0; kk < 4; kk++) {
            int cur = kk & 1, nxt = cur ^ 1;
            if (kk < 3) {
                load_afrag(As, kk + 1, afr[nxt]);
                load_bfrag(Bs, kk + 1, bfr[nxt]);
            }
            #pragma unroll
            for (int g = 0; g < 3; g++)
                #pragma unroll
                for (int mb = 0; mb < 2; mb++)
                    #pragma unroll
                    for (int nb = 0; nb < 4; nb++)
                        MMA_F16(acc[g][mb][nb], afr[cur][mb], bfr[cur][g][nb]);
        }
    }

    // ---- fused LSTM epilogue: c1 = sig(f+bf)*c0 + sig(i+bi)*tanh(c+bc) ----
    const int gr = lane >> 2, tig = lane & 3;
    #pragma unroll
    for (int mb = 0; mb < 2; mb++) {
        int row0 = m0 + wm * 32 + mb * 16 + gr;       // rows row0 and row0+8
        #pragma unroll
        for (int nb = 0; nb < 4; nb++) {
            int col = n0 + wn * 32 + nb * 8 + tig * 2;
            float2 bf = *(const float2*)(bias + col);
            float2 bi = *(const float2*)(bias + HID + col);
            float2 bc = *(const float2*)(bias + 2 * HID + col);
            float2 c0a = *(const float2*)(c0 + (size_t)row0 * HID + col);
            float2 c0b = *(const float2*)(c0 + (size_t)(row0 + 8) * HID + col);

            const float* F = acc[0][mb][nb];
            const float* I = acc[1][mb][nb];
            const float* C = acc[2][mb][nb];

            float2 o0, o1;
            o0.x = fast_sigmoid(F[0] + bf.x) * c0a.x +
                   fast_sigmoid(I[0] + bi.x) * fast_tanh(C[0] + bc.x);
            o0.y = fast_sigmoid(F[1] + bf.y) * c0a.y +
                   fast_sigmoid(I[1] + bi.y) * fast_tanh(C[1] + bc.y);
            o1.x = fast_sigmoid(F[2] + bf.x) * c0b.x +
                   fast_sigmoid(I[2] + bi.x) * fast_tanh(C[2] + bc.x);
            o1.y = fast_sigmoid(F[3] + bf.y) * c0b.y +
                   fast_sigmoid(I[3] + bi.y) * fast_tanh(C[3] + bc.y);

            *(float2*)(out + (size_t)row0 * HID + col) = o0;
            *(float2*)(out + (size_t)(row0 + 8) * HID + col) = o1;
        }
    }
}

// ---------------- host launch ----------------
extern "C" void kernel_launch(void* const* d_in, const int* in_sizes, int n_in,
                              void* d_out, int out_size) {
    const float* X    = (const float*)d_in[0];
    const float* H0   = (const float*)d_in[1];
    const float* C0   = (const float*)d_in[2];
    const float* W    = (const float*)d_in[3];
    const float* Wh   = (const float*)d_in[4];
    const float* Bias = (const float*)d_in[5];
    float* out = (float*)d_out;

    __half* bt = nullptr;
    __half* ah = nullptr;
    cudaGetSymbolAddress((void**)&bt, g_BT);
    cudaGetSymbolAddress((void**)&ah, g_AH);

    cudaFuncSetAttribute(lstm_gemm_fused, cudaFuncAttributeMaxDynamicSharedMemorySize,
                         SMEM_TOTAL);

    lstm_prep<<<CVT_BLOCKS + PACK_BLOCKS, 256>>>(X, H0, W, Wh, ah, bt);
    lstm_gemm_fused<<<dim3(HID / 64, BATCH / 64), 128, SMEM_TOTAL>>>(ah, bt, C0, Bias, out);
}